// round 6
// baseline (speedup 1.0000x reference)
#include <cuda_runtime.h>
#include <cstdint>

#define M_TOK 65536   // B*N
#define C_DIM 1024
#define H_DIM 512
#define Q_DIM 256

// ----------------- device-global scratch ----------------------------------
__device__ float g_mu[M_TOK];
__device__ float g_rstd[M_TOK];
__device__ float g_bias2[H_DIM];
__device__ float g_h1[(size_t)M_TOK * H_DIM];
__device__ float g_h2[(size_t)M_TOK * H_DIM];
__device__ float g_h3[(size_t)M_TOK * Q_DIM];
// tf32-split weights, ORIGINAL [k][n] layout
__device__ float g_W1h[C_DIM * H_DIM];
__device__ float g_W1l[C_DIM * H_DIM];
__device__ float g_W2h[H_DIM * H_DIM];
__device__ float g_W2l[H_DIM * H_DIM];
__device__ float g_W3h[H_DIM * Q_DIM];
__device__ float g_W3l[H_DIM * Q_DIM];
__device__ int   g_fix_count;
__device__ int   g_fix_list[M_TOK];

// ----------------- helpers ------------------------------------------------
__device__ __forceinline__ float gelu_f(float v) {
    return 0.5f * v * (1.0f + erff(v * 0.70710678118654752440f));
}
__device__ __forceinline__ void tf32split(float x, float& h, float& l) {
    uint32_t u;
    asm("cvt.rna.tf32.f32 %0, %1;" : "=r"(u) : "f"(x));
    h = __uint_as_float(u);
    float r = x - h;
    uint32_t u2;
    asm("cvt.rna.tf32.f32 %0, %1;" : "=r"(u2) : "f"(r));
    l = __uint_as_float(u2);
}
__device__ __forceinline__ uint32_t smem_u32(const void* p) {
    uint32_t a;
    asm("{ .reg .u64 t; cvta.to.shared.u64 t, %1; cvt.u32.u64 %0, t; }" : "=r"(a) : "l"(p));
    return a;
}
#define CPA16(dst, src) \
    asm volatile("cp.async.cg.shared.global [%0], [%1], 16;" :: "r"(dst), "l"(src) : "memory")
#define CPA_COMMIT() asm volatile("cp.async.commit_group;" ::: "memory")
#define CPA_WAIT0()  asm volatile("cp.async.wait_group 0;" ::: "memory")

__device__ __forceinline__ void mma8(float* d, const uint32_t* a, const uint32_t* b) {
    asm volatile(
        "mma.sync.aligned.m16n8k8.row.col.f32.tf32.tf32.f32 "
        "{%0,%1,%2,%3}, {%4,%5,%6,%7}, {%8,%9}, {%0,%1,%2,%3};"
        : "+f"(d[0]), "+f"(d[1]), "+f"(d[2]), "+f"(d[3])
        : "r"(a[0]), "r"(a[1]), "r"(a[2]), "r"(a[3]), "r"(b[0]), "r"(b[1]));
}

// ----------------- LN stats ------------------------------------------------
__global__ __launch_bounds__(256)
void ln_stats_kernel(const float* __restrict__ x) {
    int row = (blockIdx.x * 256 + threadIdx.x) >> 5;
    int lane = threadIdx.x & 31;
    const float4* xr = (const float4*)(x + (size_t)row * C_DIM);
    float s = 0.f, ss = 0.f;
#pragma unroll
    for (int i = 0; i < C_DIM / 128; ++i) {
        float4 v = xr[lane + 32 * i];
        s  += v.x + v.y + v.z + v.w;
        ss += v.x * v.x + v.y * v.y + v.z * v.z + v.w * v.w;
    }
#pragma unroll
    for (int o = 16; o; o >>= 1) {
        s  += __shfl_xor_sync(0xffffffffu, s, o);
        ss += __shfl_xor_sync(0xffffffffu, ss, o);
    }
    if (lane == 0) {
        float mu = s * (1.0f / C_DIM);
        float var = ss * (1.0f / C_DIM) - mu * mu;
        g_mu[row] = mu;
        g_rstd[row] = rsqrtf(var + 1e-5f);
    }
}

// ----------------- weight prep: elementwise tf32 split ----------------------
__global__ void prep_w_kernel(const float* __restrict__ WL,
                              const float* __restrict__ Wl1,
                              const float* __restrict__ Wl2) {
    int i = blockIdx.x * blockDim.x + threadIdx.x;
    if (i == 0) g_fix_count = 0;
    const int S1 = C_DIM * H_DIM;           // 524288
    const int S2 = S1 + H_DIM * H_DIM;      // 786432 (Wl1 top half = first 512 rows)
    const int S3 = S2 + H_DIM * Q_DIM;      // 917504
    if (i < S1) {
        tf32split(WL[i], g_W1h[i], g_W1l[i]);
    } else if (i < S2) {
        int j = i - S1;
        tf32split(Wl1[j], g_W2h[j], g_W2l[j]);
    } else if (i < S3) {
        int j = i - S2;
        tf32split(Wl2[j], g_W3h[j], g_W3l[j]);
    }
}

// ----------------- bias2 = noise_feature @ W_l1[512:,:] --------------------
__global__ void bias2_kernel(const float* __restrict__ nf,
                             const float* __restrict__ Wl1) {
    int j = blockIdx.x * blockDim.x + threadIdx.x;
    const float* wp = Wl1 + (size_t)H_DIM * H_DIM + j;
    float s = 0.f;
    for (int k = 0; k < H_DIM; ++k)
        s += nf[k] * wp[(size_t)k * H_DIM];
    g_bias2[j] = s;
}

// ----------------- split-TF32 mma.sync GEMM ---------------------------------
// smem float layout: [0,128) mu, [128,256) rstd,
//   A tiles @256: per buf 9216 floats (Ah 128x36=4608, Al 4608)
//   B tiles @18688: per buf 8704 floats (Bh 32x136=4352, Bl 4352)
#define SM_A   256
#define SM_B   18688
#define GEMM_SMEM ((SM_B + 2 * 8704) * 4)   // 144384 bytes

template <int MODE>
__global__ __launch_bounds__(256, 1)
void gemm_mma(const float* __restrict__ Aext,
              const float* __restrict__ lns, const float* __restrict__ lnb) {
    constexpr int K  = (MODE == 0) ? C_DIM : H_DIM;
    constexpr int Nn = (MODE == 2) ? Q_DIM : H_DIM;
    constexpr int KB = K / 32;

    extern __shared__ float sm[];
    const uint32_t sb = smem_u32(sm);
    const int tid = threadIdx.x;
    const int wid = tid >> 5, lane = tid & 31;
    const int g = lane >> 2, tg = lane & 3;
    const int wm = wid & 3, wn = wid >> 2;
    const int m0 = blockIdx.y * 128, n0 = blockIdx.x * 128;

    const float* A   = (MODE == 0) ? Aext : (MODE == 1 ? g_h1 : g_h2);
    const float* BhG = (MODE == 0) ? g_W1h : (MODE == 1 ? g_W2h : g_W3h);
    const float* BlG = (MODE == 0) ? g_W1l : (MODE == 1 ? g_W2l : g_W3l);
    float* Cm        = (MODE == 0) ? g_h1 : (MODE == 1 ? g_h2 : g_h3);

    if (MODE == 0 && tid < 128) {
        sm[tid]       = g_mu[m0 + tid];
        sm[128 + tid] = g_rstd[m0 + tid];
    }

    // A staging map: thread -> (row, 16-wide k half)
    const int arow = tid >> 1;
    const int ak   = (tid & 1) * 16;
    const float* aP = A + (size_t)(m0 + arow) * K + ak;
    // B staging map: thread -> (k row, 16B col group), 4 col groups of 32
    const int bk = tid >> 3;
    const int bc = (tid & 7) * 4;
    const float* bhP = BhG + (size_t)bk * Nn + n0 + bc;
    const float* blP = BlG + (size_t)bk * Nn + n0 + bc;

    float4 aR[4];

    auto issueB = [&](int kb, int b) {
        uint32_t dh = sb + (uint32_t)(SM_B + b * 8704 + bk * 136 + bc) * 4;
        uint32_t dl = dh + 4352u * 4;
        const float* sh = bhP + (size_t)kb * 32 * Nn;
        const float* sl = blP + (size_t)kb * 32 * Nn;
#pragma unroll
        for (int j = 0; j < 4; ++j) {
            CPA16(dh + j * 128, sh + j * 32);
            CPA16(dl + j * 128, sl + j * 32);
        }
    };
    auto loadA = [&](int kb) {
        const float* p = aP + kb * 32;
#pragma unroll
        for (int c = 0; c < 4; ++c) aR[c] = *(const float4*)(p + c * 4);
    };
    auto storeA = [&](int kb, int b) {
        float* dh = sm + SM_A + b * 9216 + arow * 36 + ak;
        float* dl = dh + 4608;
        float mu = 0.f, rs = 0.f;
        if (MODE == 0) { mu = sm[arow]; rs = sm[128 + arow]; }
#pragma unroll
        for (int c = 0; c < 4; ++c) {
            float4 v = aR[c];
            if (MODE == 0) {
                int k = kb * 32 + ak + c * 4;
                float4 s4 = *(const float4*)(lns + k);
                float4 b4 = *(const float4*)(lnb + k);
                v.x = (v.x - mu) * rs * s4.x + b4.x;
                v.y = (v.y - mu) * rs * s4.y + b4.y;
                v.z = (v.z - mu) * rs * s4.z + b4.z;
                v.w = (v.w - mu) * rs * s4.w + b4.w;
            }
            float4 h4, l4;
            tf32split(v.x, h4.x, l4.x);
            tf32split(v.y, h4.y, l4.y);
            tf32split(v.z, h4.z, l4.z);
            tf32split(v.w, h4.w, l4.w);
            *(float4*)(dh + c * 4) = h4;
            *(float4*)(dl + c * 4) = l4;
        }
    };

    float acc[2][8][4];
#pragma unroll
    for (int mt = 0; mt < 2; ++mt)
#pragma unroll
        for (int nt = 0; nt < 8; ++nt)
#pragma unroll
            for (int j = 0; j < 4; ++j) acc[mt][nt][j] = 0.f;

    auto compute = [&](int b) {
        const float* Ah = sm + SM_A + b * 9216;
        const float* Al = Ah + 4608;
        const float* Bh = sm + SM_B + b * 8704;
        const float* Bl = Bh + 4352;
#pragma unroll
        for (int kc = 0; kc < 4; ++kc) {
            const int kk = kc * 8 + tg;
            uint32_t ah[2][4], al[2][4], bh[8][2], bl[8][2];
#pragma unroll
            for (int mt = 0; mt < 2; ++mt) {
                int r = wm * 32 + mt * 16 + g;
                const float* p0 = Ah + r * 36 + kk;
                const float* p1 = Al + r * 36 + kk;
                ah[mt][0] = __float_as_uint(p0[0]);
                ah[mt][1] = __float_as_uint(p0[8 * 36]);
                ah[mt][2] = __float_as_uint(p0[4]);
                ah[mt][3] = __float_as_uint(p0[8 * 36 + 4]);
                al[mt][0] = __float_as_uint(p1[0]);
                al[mt][1] = __float_as_uint(p1[8 * 36]);
                al[mt][2] = __float_as_uint(p1[4]);
                al[mt][3] = __float_as_uint(p1[8 * 36 + 4]);
            }
#pragma unroll
            for (int nt = 0; nt < 8; ++nt) {
                int c = wn * 64 + nt * 8 + g;
                const float* q0 = Bh + kk * 136 + c;
                const float* q1 = Bl + kk * 136 + c;
                bh[nt][0] = __float_as_uint(q0[0]);
                bh[nt][1] = __float_as_uint(q0[4 * 136]);
                bl[nt][0] = __float_as_uint(q1[0]);
                bl[nt][1] = __float_as_uint(q1[4 * 136]);
            }
#pragma unroll
            for (int mt = 0; mt < 2; ++mt)
#pragma unroll
                for (int nt = 0; nt < 8; ++nt) {
                    mma8(acc[mt][nt], ah[mt], bh[nt]);
                    mma8(acc[mt][nt], ah[mt], bl[nt]);
                    mma8(acc[mt][nt], al[mt], bh[nt]);
                }
        }
    };

    // ---- pipeline ----
    issueB(0, 0);
    CPA_COMMIT();
    loadA(0);
    __syncthreads();          // mu/rstd visible for storeA
    storeA(0, 0);
    CPA_WAIT0();
    __syncthreads();

    int buf = 0;
    for (int kt = 0; kt < KB; ++kt) {
        if (kt + 1 < KB) {
            issueB(kt + 1, buf ^ 1);
            CPA_COMMIT();
            loadA(kt + 1);
        }
        compute(buf);
        if (kt + 1 < KB) storeA(kt + 1, buf ^ 1);
        CPA_WAIT0();
        __syncthreads();
        buf ^= 1;
    }

    // ---- epilogue: gelu (+bias for MODE 1), float2 stores ----
#pragma unroll
    for (int mt = 0; mt < 2; ++mt) {
        int r = m0 + wm * 32 + mt * 16 + g;
#pragma unroll
        for (int nt = 0; nt < 8; ++nt) {
            int c = n0 + wn * 64 + nt * 8 + tg * 2;
            float* a4 = acc[mt][nt];
            float b0 = 0.f, b1 = 0.f;
            if (MODE == 1) { b0 = g_bias2[c]; b1 = g_bias2[c + 1]; }
            float2 v0 = make_float2(gelu_f(a4[0] + b0), gelu_f(a4[1] + b1));
            float2 v1 = make_float2(gelu_f(a4[2] + b0), gelu_f(a4[3] + b1));
            *(float2*)(Cm + (size_t)r * Nn + c)       = v0;
            *(float2*)(Cm + (size_t)(r + 8) * Nn + c) = v1;
        }
    }
}

// ----------------- final: logit, flag-or-write -----------------------------
__global__ __launch_bounds__(256)
void final_kernel(const float* __restrict__ x, const float* __restrict__ prevm,
                  const float* __restrict__ w3, float* __restrict__ out,
                  int write_extra) {
    int row = (blockIdx.x * 256 + threadIdx.x) >> 5;
    int lane = threadIdx.x & 31;
    const float* h3 = g_h3 + (size_t)row * Q_DIM;
    float s = 0.f;
#pragma unroll
    for (int i = 0; i < 8; ++i) s += h3[lane + 32 * i] * w3[lane + 32 * i];
#pragma unroll
    for (int o = 16; o; o >>= 1) s += __shfl_xor_sync(0xffffffffu, s, o);

    float prob = 1.0f / (1.0f + expf(-s));
    float xm = prob * prevm[row];

    if (fabsf(xm - 0.5f) < 5e-4f) {
        if (lane == 0) {
            int idx = atomicAdd(&g_fix_count, 1);
            if (idx < M_TOK) g_fix_list[idx] = row;
        }
        return;
    }
    float m = (xm > 0.5f) ? 1.0f : 0.0f;
    if (lane == 0 && write_extra) {
        out[(size_t)M_TOK * C_DIM + row] = m;
        out[(size_t)M_TOK * C_DIM + M_TOK + row] = (m > 0.f) ? 1.0f : 1e-10f;
    }
    const float4* xr = (const float4*)(x + (size_t)row * C_DIM);
    float4* orow = (float4*)(out + (size_t)row * C_DIM);
#pragma unroll
    for (int i = 0; i < 8; ++i) {
        float4 v = xr[lane + 32 * i];
        v.x *= m; v.y *= m; v.z *= m; v.w *= m;
        orow[lane + 32 * i] = v;
    }
}

// ----------------- fixup: exact fp32 recompute for flagged rows ------------
__global__ __launch_bounds__(256)
void fixup_kernel(const float* __restrict__ x, const float* __restrict__ prevm,
                  const float* __restrict__ WL, const float* __restrict__ Wl1,
                  const float* __restrict__ Wl2, const float* __restrict__ w3,
                  const float* __restrict__ lns, const float* __restrict__ lnb,
                  float* __restrict__ out, int write_extra) {
    __shared__ float a[C_DIM];
    __shared__ float h1s[H_DIM];
    __shared__ float h2s[H_DIM];
    __shared__ float h3s[Q_DIM];
    __shared__ float red[256];
    int cnt = g_fix_count;
    if (cnt > M_TOK) cnt = M_TOK;
    int t = threadIdx.x;

    for (int i = blockIdx.x; i < cnt; i += gridDim.x) {
        int row = g_fix_list[i];
        float mu = g_mu[row], rs = g_rstd[row];
        for (int j = t; j < C_DIM; j += 256)
            a[j] = (x[(size_t)row * C_DIM + j] - mu) * rs * lns[j] + lnb[j];
        __syncthreads();
        for (int j = t; j < H_DIM; j += 256) {
            float acc = 0.f;
            for (int k = 0; k < C_DIM; ++k)
                acc = fmaf(a[k], WL[(size_t)k * H_DIM + j], acc);
            h1s[j] = gelu_f(acc);
        }
        __syncthreads();
        for (int j = t; j < H_DIM; j += 256) {
            float acc = g_bias2[j];
            for (int k = 0; k < H_DIM; ++k)
                acc = fmaf(h1s[k], Wl1[(size_t)k * H_DIM + j], acc);
            h2s[j] = gelu_f(acc);
        }
        __syncthreads();
        for (int j = t; j < Q_DIM; j += 256) {
            float acc = 0.f;
            for (int k = 0; k < H_DIM; ++k)
                acc = fmaf(h2s[k], Wl2[(size_t)k * Q_DIM + j], acc);
            h3s[j] = gelu_f(acc);
        }
        __syncthreads();
        red[t] = (t < Q_DIM) ? h3s[t] * w3[t] : 0.f;
        __syncthreads();
        for (int o = 128; o; o >>= 1) {
            if (t < o) red[t] += red[t + o];
            __syncthreads();
        }
        float s = red[0];
        float prob = 1.0f / (1.0f + expf(-s));
        float m = (prob * prevm[row] > 0.5f) ? 1.0f : 0.0f;
        if (t == 0 && write_extra) {
            out[(size_t)M_TOK * C_DIM + row] = m;
            out[(size_t)M_TOK * C_DIM + M_TOK + row] = (m > 0.f) ? 1.0f : 1e-10f;
        }
        for (int j = t; j < C_DIM; j += 256)
            out[(size_t)row * C_DIM + j] = x[(size_t)row * C_DIM + j] * m;
        __syncthreads();
    }
}

// ----------------- launch ---------------------------------------------------
extern "C" void kernel_launch(void* const* d_in, const int* in_sizes, int n_in,
                              void* d_out, int out_size) {
    const float* x   = (const float*)d_in[0];
    const float* nf  = (const float*)d_in[1];
    const float* pm  = (const float*)d_in[2];
    const float* lns = (const float*)d_in[3];
    const float* lnb = (const float*)d_in[4];
    const float* WL  = (const float*)d_in[5];
    const float* Wl1 = (const float*)d_in[6];
    const float* Wl2 = (const float*)d_in[7];
    const float* W3  = (const float*)d_in[8];
    float* out = (float*)d_out;

    cudaFuncSetAttribute(gemm_mma<0>, cudaFuncAttributeMaxDynamicSharedMemorySize, GEMM_SMEM);
    cudaFuncSetAttribute(gemm_mma<1>, cudaFuncAttributeMaxDynamicSharedMemorySize, GEMM_SMEM);
    cudaFuncSetAttribute(gemm_mma<2>, cudaFuncAttributeMaxDynamicSharedMemorySize, GEMM_SMEM);

    ln_stats_kernel<<<M_TOK / 8, 256>>>(x);
    prep_w_kernel<<<(C_DIM * H_DIM + H_DIM * H_DIM + H_DIM * Q_DIM + 255) / 256, 256>>>(WL, Wl1, Wl2);
    bias2_kernel<<<2, 256>>>(nf, Wl1);

    gemm_mma<0><<<dim3(H_DIM / 128, M_TOK / 128), 256, GEMM_SMEM>>>(x, lns, lnb);
    gemm_mma<1><<<dim3(H_DIM / 128, M_TOK / 128), 256, GEMM_SMEM>>>(nullptr, nullptr, nullptr);
    gemm_mma<2><<<dim3(Q_DIM / 128, M_TOK / 128), 256, GEMM_SMEM>>>(nullptr, nullptr, nullptr);

    int extra = (out_size >= M_TOK * C_DIM + 2 * M_TOK) ? 1 : 0;
    final_kernel<<<M_TOK / 8, 256>>>(x, pm, W3, out, extra);
    fixup_kernel<<<512, 256>>>(x, pm, WL, Wl1, Wl2, W3, lns, lnb, out, extra);
}

// round 7
// speedup vs baseline: 1.7438x; 1.7438x over previous
#include <cuda_runtime.h>
#include <cuda_fp16.h>
#include <cstdint>

#define M_TOK 65536   // B*N
#define C_DIM 1024
#define H_DIM 512
#define Q_DIM 256

// ----------------- device-global scratch ----------------------------------
__device__ float g_mu[M_TOK];
__device__ float g_rstd[M_TOK];
__device__ float g_bias2[H_DIM];
__device__ float g_h1[(size_t)M_TOK * H_DIM];
__device__ float g_h2[(size_t)M_TOK * H_DIM];
__device__ float g_h3[(size_t)M_TOK * Q_DIM];
// fp16-split weights, TRANSPOSED [n][k] layout (k contiguous)
__device__ __half g_W1h[H_DIM * C_DIM];
__device__ __half g_W1l[H_DIM * C_DIM];
__device__ __half g_W2h[H_DIM * H_DIM];
__device__ __half g_W2l[H_DIM * H_DIM];
__device__ __half g_W3h[Q_DIM * H_DIM];
__device__ __half g_W3l[Q_DIM * H_DIM];
__device__ int   g_fix_count;
__device__ int   g_fix_list[M_TOK];

// ----------------- helpers ------------------------------------------------
__device__ __forceinline__ float gelu_f(float v) {
    return 0.5f * v * (1.0f + erff(v * 0.70710678118654752440f));
}
__device__ __forceinline__ void h16split(float x, __half& h, __half& l) {
    h = __float2half_rn(x);
    l = __float2half_rn(x - __half2float(h));
}
__device__ __forceinline__ uint32_t pack2(__half a, __half b) {
    __half2 h2 = __halves2half2(a, b);
    return *reinterpret_cast<uint32_t*>(&h2);
}
#define CPA16(dst, src) \
    asm volatile("cp.async.cg.shared.global [%0], [%1], 16;" :: "r"(dst), "l"(src) : "memory")
#define CPA_COMMIT() asm volatile("cp.async.commit_group;" ::: "memory")
#define CPA_WAIT0()  asm volatile("cp.async.wait_group 0;" ::: "memory")
__device__ __forceinline__ uint32_t smem_u32(const void* p) {
    uint32_t a;
    asm("{ .reg .u64 t; cvta.to.shared.u64 t, %1; cvt.u32.u64 %0, t; }" : "=r"(a) : "l"(p));
    return a;
}
__device__ __forceinline__ void mma16(float* d, const uint32_t* a, uint32_t b0, uint32_t b1) {
    asm volatile(
        "mma.sync.aligned.m16n8k16.row.col.f32.f16.f16.f32 "
        "{%0,%1,%2,%3}, {%4,%5,%6,%7}, {%8,%9}, {%0,%1,%2,%3};"
        : "+f"(d[0]), "+f"(d[1]), "+f"(d[2]), "+f"(d[3])
        : "r"(a[0]), "r"(a[1]), "r"(a[2]), "r"(a[3]), "r"(b0), "r"(b1));
}

// ----------------- LN stats ------------------------------------------------
__global__ __launch_bounds__(256)
void ln_stats_kernel(const float* __restrict__ x) {
    int row = (blockIdx.x * 256 + threadIdx.x) >> 5;
    int lane = threadIdx.x & 31;
    const float4* xr = (const float4*)(x + (size_t)row * C_DIM);
    float s = 0.f, ss = 0.f;
#pragma unroll
    for (int i = 0; i < C_DIM / 128; ++i) {
        float4 v = xr[lane + 32 * i];
        s  += v.x + v.y + v.z + v.w;
        ss += v.x * v.x + v.y * v.y + v.z * v.z + v.w * v.w;
    }
#pragma unroll
    for (int o = 16; o; o >>= 1) {
        s  += __shfl_xor_sync(0xffffffffu, s, o);
        ss += __shfl_xor_sync(0xffffffffu, ss, o);
    }
    if (lane == 0) {
        float mu = s * (1.0f / C_DIM);
        float var = ss * (1.0f / C_DIM) - mu * mu;
        g_mu[row] = mu;
        g_rstd[row] = rsqrtf(var + 1e-5f);
    }
}

// ----------------- weight prep: transpose + fp16 split ----------------------
__global__ void prep_w_kernel(const float* __restrict__ WL,
                              const float* __restrict__ Wl1,
                              const float* __restrict__ Wl2) {
    int i = blockIdx.x * blockDim.x + threadIdx.x;
    if (i == 0) g_fix_count = 0;
    const int S1 = H_DIM * C_DIM;
    const int S2 = S1 + H_DIM * H_DIM;
    const int S3 = S2 + Q_DIM * H_DIM;
    if (i < S1) {
        int n = i / C_DIM, k = i % C_DIM;
        h16split(WL[(size_t)k * H_DIM + n], g_W1h[i], g_W1l[i]);
    } else if (i < S2) {
        int j = i - S1;
        int n = j / H_DIM, k = j % H_DIM;          // Wl1 top half: rows 0..511
        h16split(Wl1[(size_t)k * H_DIM + n], g_W2h[j], g_W2l[j]);
    } else if (i < S3) {
        int j = i - S2;
        int n = j / H_DIM, k = j % H_DIM;
        h16split(Wl2[(size_t)k * Q_DIM + n], g_W3h[j], g_W3l[j]);
    }
}

// ----------------- bias2 = noise_feature @ W_l1[512:,:] (exact fp32) -------
__global__ void bias2_kernel(const float* __restrict__ nf,
                             const float* __restrict__ Wl1) {
    int j = blockIdx.x * blockDim.x + threadIdx.x;
    const float* wp = Wl1 + (size_t)H_DIM * H_DIM + j;
    float s = 0.f;
    for (int k = 0; k < H_DIM; ++k)
        s += nf[k] * wp[(size_t)k * H_DIM];
    g_bias2[j] = s;
}

// ----------------- split-fp16 mma.sync GEMM ---------------------------------
// smem bytes: [0,1024): mu(128f)+rstd(128f)
//   A: base 1024, per buf 20480 (Ah 128x80B=10240, Al 10240), 2 bufs -> 41984
//   B: base 41984, per buf 20480 (Bh 128x80B, Bl), 2 bufs -> 82944
#define AB0 1024
#define BB0 41984
#define GEMM_SMEM 82944

template <int MODE>
__global__ __launch_bounds__(256, 2)
void gemm_mma(const float* __restrict__ Aext,
              const float* __restrict__ lns, const float* __restrict__ lnb) {
    constexpr int K  = (MODE == 0) ? C_DIM : H_DIM;
    constexpr int Nn = (MODE == 2) ? Q_DIM : H_DIM;
    constexpr int KB = K / 32;

    extern __shared__ char sm[];
    float* smf = (float*)sm;
    const uint32_t sb = smem_u32(sm);
    const int tid = threadIdx.x;
    const int wid = tid >> 5, lane = tid & 31;
    const int g = lane >> 2, tg = lane & 3;
    const int wm = wid & 3, wn = wid >> 2;
    const int m0 = blockIdx.y * 128, n0 = blockIdx.x * 128;

    const float* A    = (MODE == 0) ? Aext : (MODE == 1 ? g_h1 : g_h2);
    const __half* BhG = (MODE == 0) ? g_W1h : (MODE == 1 ? g_W2h : g_W3h);
    const __half* BlG = (MODE == 0) ? g_W1l : (MODE == 1 ? g_W2l : g_W3l);
    float* Cm         = (MODE == 0) ? g_h1 : (MODE == 1 ? g_h2 : g_h3);

    if (MODE == 0 && tid < 128) {
        smf[tid]       = g_mu[m0 + tid];
        smf[128 + tid] = g_rstd[m0 + tid];
    }

    // A staging: thread -> (row arow, 16-wide k half)
    const int arow = tid >> 1;
    const int ak   = (tid & 1) * 16;
    const float* aP = A + (size_t)(m0 + arow) * K + ak;
    // B staging: thread -> rows brow, brow+64; 16B chunk bq of 4
    const int brow = tid >> 2;
    const int bq   = tid & 3;
    const __half* bhP = BhG + (size_t)(n0 + brow) * K + bq * 8;
    const __half* blP = BlG + (size_t)(n0 + brow) * K + bq * 8;

    float4 aR[4];

    auto issueB = [&](int kb, int b) {
        uint32_t base = sb + BB0 + b * 20480 + brow * 80 + bq * 16;
        const __half* sh = bhP + kb * 32;
        const __half* sl = blP + kb * 32;
        CPA16(base,                 sh);
        CPA16(base + 64 * 80,       sh + (size_t)64 * K);
        CPA16(base + 10240,         sl);
        CPA16(base + 10240 + 64*80, sl + (size_t)64 * K);
    };
    auto loadA = [&](int kb) {
        const float* p = aP + kb * 32;
#pragma unroll
        for (int c = 0; c < 4; ++c) aR[c] = *(const float4*)(p + c * 4);
    };
    auto storeA = [&](int kb, int b) {
        char* dh = sm + AB0 + b * 20480 + arow * 80 + ak * 2;
        char* dl = dh + 10240;
        float mu = 0.f, rs = 0.f;
        if (MODE == 0) { mu = smf[arow]; rs = smf[128 + arow]; }
        uint32_t hw[8], lw[8];
#pragma unroll
        for (int c = 0; c < 4; ++c) {
            float4 v = aR[c];
            if (MODE == 0) {
                int k = kb * 32 + ak + c * 4;
                float4 s4 = *(const float4*)(lns + k);
                float4 b4 = *(const float4*)(lnb + k);
                v.x = (v.x - mu) * rs * s4.x + b4.x;
                v.y = (v.y - mu) * rs * s4.y + b4.y;
                v.z = (v.z - mu) * rs * s4.z + b4.z;
                v.w = (v.w - mu) * rs * s4.w + b4.w;
            }
            __half hx, lx, hy, ly, hz, lz, hwv, lwv;
            h16split(v.x, hx, lx); h16split(v.y, hy, ly);
            h16split(v.z, hz, lz); h16split(v.w, hwv, lwv);
            hw[c * 2]     = pack2(hx, hy);
            hw[c * 2 + 1] = pack2(hz, hwv);
            lw[c * 2]     = pack2(lx, ly);
            lw[c * 2 + 1] = pack2(lz, lwv);
        }
        *(uint4*)(dh)      = make_uint4(hw[0], hw[1], hw[2], hw[3]);
        *(uint4*)(dh + 16) = make_uint4(hw[4], hw[5], hw[6], hw[7]);
        *(uint4*)(dl)      = make_uint4(lw[0], lw[1], lw[2], lw[3]);
        *(uint4*)(dl + 16) = make_uint4(lw[4], lw[5], lw[6], lw[7]);
    };

    float acc[2][8][4];
#pragma unroll
    for (int mt = 0; mt < 2; ++mt)
#pragma unroll
        for (int nt = 0; nt < 8; ++nt)
#pragma unroll
            for (int j = 0; j < 4; ++j) acc[mt][nt][j] = 0.f;

    auto compute = [&](int b) {
        const char* Ah = sm + AB0 + b * 20480;
        const char* Al = Ah + 10240;
        const char* Bh = sm + BB0 + b * 20480;
        const char* Bl = Bh + 10240;
#pragma unroll
        for (int ck = 0; ck < 2; ++ck) {
            const int ko = ck * 32 + tg * 4;     // byte offset of k pair
            uint32_t ah[2][4], al[2][4];
#pragma unroll
            for (int mt = 0; mt < 2; ++mt) {
                int r = wm * 32 + mt * 16 + g;
                const char* p0 = Ah + r * 80 + ko;
                const char* p1 = Al + r * 80 + ko;
                ah[mt][0] = *(const uint32_t*)(p0);
                ah[mt][1] = *(const uint32_t*)(p0 + 8 * 80);
                ah[mt][2] = *(const uint32_t*)(p0 + 16);
                ah[mt][3] = *(const uint32_t*)(p0 + 8 * 80 + 16);
                al[mt][0] = *(const uint32_t*)(p1);
                al[mt][1] = *(const uint32_t*)(p1 + 8 * 80);
                al[mt][2] = *(const uint32_t*)(p1 + 16);
                al[mt][3] = *(const uint32_t*)(p1 + 8 * 80 + 16);
            }
#pragma unroll
            for (int nt = 0; nt < 8; ++nt) {
                int c = wn * 64 + nt * 8 + g;
                const char* q0 = Bh + c * 80 + ko;
                const char* q1 = Bl + c * 80 + ko;
                uint32_t b0h = *(const uint32_t*)(q0);
                uint32_t b1h = *(const uint32_t*)(q0 + 16);
                uint32_t b0l = *(const uint32_t*)(q1);
                uint32_t b1l = *(const uint32_t*)(q1 + 16);
#pragma unroll
                for (int mt = 0; mt < 2; ++mt) {
                    mma16(acc[mt][nt], ah[mt], b0h, b1h);
                    mma16(acc[mt][nt], ah[mt], b0l, b1l);
                    mma16(acc[mt][nt], al[mt], b0h, b1h);
                }
            }
        }
    };

    // ---- pipeline ----
    issueB(0, 0);
    CPA_COMMIT();
    loadA(0);
    __syncthreads();          // mu/rstd visible
    storeA(0, 0);
    CPA_WAIT0();
    __syncthreads();

    int buf = 0;
    for (int kt = 0; kt < KB; ++kt) {
        if (kt + 1 < KB) {
            issueB(kt + 1, buf ^ 1);
            CPA_COMMIT();
            loadA(kt + 1);
        }
        compute(buf);
        if (kt + 1 < KB) storeA(kt + 1, buf ^ 1);
        CPA_WAIT0();
        __syncthreads();
        buf ^= 1;
    }

    // ---- epilogue ----
#pragma unroll
    for (int mt = 0; mt < 2; ++mt) {
        int r = m0 + wm * 32 + mt * 16 + g;
#pragma unroll
        for (int nt = 0; nt < 8; ++nt) {
            int c = n0 + wn * 64 + nt * 8 + tg * 2;
            float* a4 = acc[mt][nt];
            float b0 = 0.f, b1 = 0.f;
            if (MODE == 1) { b0 = g_bias2[c]; b1 = g_bias2[c + 1]; }
            float2 v0 = make_float2(gelu_f(a4[0] + b0), gelu_f(a4[1] + b1));
            float2 v1 = make_float2(gelu_f(a4[2] + b0), gelu_f(a4[3] + b1));
            *(float2*)(Cm + (size_t)r * Nn + c)       = v0;
            *(float2*)(Cm + (size_t)(r + 8) * Nn + c) = v1;
        }
    }
}

// ----------------- final: logit, flag-or-write -----------------------------
__global__ __launch_bounds__(256)
void final_kernel(const float* __restrict__ x, const float* __restrict__ prevm,
                  const float* __restrict__ w3, float* __restrict__ out,
                  int write_extra) {
    int row = (blockIdx.x * 256 + threadIdx.x) >> 5;
    int lane = threadIdx.x & 31;
    const float* h3 = g_h3 + (size_t)row * Q_DIM;
    float s = 0.f;
#pragma unroll
    for (int i = 0; i < 8; ++i) s += h3[lane + 32 * i] * w3[lane + 32 * i];
#pragma unroll
    for (int o = 16; o; o >>= 1) s += __shfl_xor_sync(0xffffffffu, s, o);

    float prob = 1.0f / (1.0f + expf(-s));
    float xm = prob * prevm[row];

    if (fabsf(xm - 0.5f) < 2e-4f) {
        if (lane == 0) {
            int idx = atomicAdd(&g_fix_count, 1);
            if (idx < M_TOK) g_fix_list[idx] = row;
        }
        return;
    }
    float m = (xm > 0.5f) ? 1.0f : 0.0f;
    if (lane == 0 && write_extra) {
        out[(size_t)M_TOK * C_DIM + row] = m;
        out[(size_t)M_TOK * C_DIM + M_TOK + row] = (m > 0.f) ? 1.0f : 1e-10f;
    }
    const float4* xr = (const float4*)(x + (size_t)row * C_DIM);
    float4* orow = (float4*)(out + (size_t)row * C_DIM);
#pragma unroll
    for (int i = 0; i < 8; ++i) {
        float4 v = xr[lane + 32 * i];
        v.x *= m; v.y *= m; v.z *= m; v.w *= m;
        orow[lane + 32 * i] = v;
    }
}

// ----------------- fixup: exact fp32 recompute for flagged rows ------------
__global__ __launch_bounds__(256)
void fixup_kernel(const float* __restrict__ x, const float* __restrict__ prevm,
                  const float* __restrict__ WL, const float* __restrict__ Wl1,
                  const float* __restrict__ Wl2, const float* __restrict__ w3,
                  const float* __restrict__ lns, const float* __restrict__ lnb,
                  float* __restrict__ out, int write_extra) {
    __shared__ float a[C_DIM];
    __shared__ float h1s[H_DIM];
    __shared__ float h2s[H_DIM];
    __shared__ float h3s[Q_DIM];
    __shared__ float red[256];
    int cnt = g_fix_count;
    if (cnt > M_TOK) cnt = M_TOK;
    int t = threadIdx.x;

    for (int i = blockIdx.x; i < cnt; i += gridDim.x) {
        int row = g_fix_list[i];
        float mu = g_mu[row], rs = g_rstd[row];
        for (int j = t; j < C_DIM; j += 256)
            a[j] = (x[(size_t)row * C_DIM + j] - mu) * rs * lns[j] + lnb[j];
        __syncthreads();
        for (int j = t; j < H_DIM; j += 256) {
            float acc = 0.f;
            for (int k = 0; k < C_DIM; ++k)
                acc = fmaf(a[k], WL[(size_t)k * H_DIM + j], acc);
            h1s[j] = gelu_f(acc);
        }
        __syncthreads();
        for (int j = t; j < H_DIM; j += 256) {
            float acc = g_bias2[j];
            for (int k = 0; k < H_DIM; ++k)
                acc = fmaf(h1s[k], Wl1[(size_t)k * H_DIM + j], acc);
            h2s[j] = gelu_f(acc);
        }
        __syncthreads();
        for (int j = t; j < Q_DIM; j += 256) {
            float acc = 0.f;
            for (int k = 0; k < H_DIM; ++k)
                acc = fmaf(h2s[k], Wl2[(size_t)k * Q_DIM + j], acc);
            h3s[j] = gelu_f(acc);
        }
        __syncthreads();
        red[t] = (t < Q_DIM) ? h3s[t] * w3[t] : 0.f;
        __syncthreads();
        for (int o = 128; o; o >>= 1) {
            if (t < o) red[t] += red[t + o];
            __syncthreads();
        }
        float s = red[0];
        float prob = 1.0f / (1.0f + expf(-s));
        float m = (prob * prevm[row] > 0.5f) ? 1.0f : 0.0f;
        if (t == 0 && write_extra) {
            out[(size_t)M_TOK * C_DIM + row] = m;
            out[(size_t)M_TOK * C_DIM + M_TOK + row] = (m > 0.f) ? 1.0f : 1e-10f;
        }
        for (int j = t; j < C_DIM; j += 256)
            out[(size_t)row * C_DIM + j] = x[(size_t)row * C_DIM + j] * m;
        __syncthreads();
    }
}

// ----------------- launch ---------------------------------------------------
extern "C" void kernel_launch(void* const* d_in, const int* in_sizes, int n_in,
                              void* d_out, int out_size) {
    const float* x   = (const float*)d_in[0];
    const float* nf  = (const float*)d_in[1];
    const float* pm  = (const float*)d_in[2];
    const float* lns = (const float*)d_in[3];
    const float* lnb = (const float*)d_in[4];
    const float* WL  = (const float*)d_in[5];
    const float* Wl1 = (const float*)d_in[6];
    const float* Wl2 = (const float*)d_in[7];
    const float* W3  = (const float*)d_in[8];
    float* out = (float*)d_out;

    cudaFuncSetAttribute(gemm_mma<0>, cudaFuncAttributeMaxDynamicSharedMemorySize, GEMM_SMEM);
    cudaFuncSetAttribute(gemm_mma<1>, cudaFuncAttributeMaxDynamicSharedMemorySize, GEMM_SMEM);
    cudaFuncSetAttribute(gemm_mma<2>, cudaFuncAttributeMaxDynamicSharedMemorySize, GEMM_SMEM);

    ln_stats_kernel<<<M_TOK / 8, 256>>>(x);
    prep_w_kernel<<<(H_DIM * C_DIM + H_DIM * H_DIM + Q_DIM * H_DIM + 255) / 256, 256>>>(WL, Wl1, Wl2);
    bias2_kernel<<<2, 256>>>(nf, Wl1);

    gemm_mma<0><<<dim3(H_DIM / 128, M_TOK / 128), 256, GEMM_SMEM>>>(x, lns, lnb);
    gemm_mma<1><<<dim3(H_DIM / 128, M_TOK / 128), 256, GEMM_SMEM>>>(nullptr, nullptr, nullptr);
    gemm_mma<2><<<dim3(Q_DIM / 128, M_TOK / 128), 256, GEMM_SMEM>>>(nullptr, nullptr, nullptr);

    int extra = (out_size >= M_TOK * C_DIM + 2 * M_TOK) ? 1 : 0;
    final_kernel<<<M_TOK / 8, 256>>>(x, pm, W3, out, extra);
    fixup_kernel<<<512, 256>>>(x, pm, WL, Wl1, Wl2, W3, lns, lnb, out, extra);
}

// round 8
// speedup vs baseline: 1.8489x; 1.0603x over previous
#include <cuda_runtime.h>
#include <cuda_fp16.h>
#include <cstdint>

#define M_TOK 65536   // B*N
#define C_DIM 1024
#define H_DIM 512
#define Q_DIM 256

// ----------------- device-global scratch ----------------------------------
__device__ float g_mu[M_TOK];
__device__ float g_rstd[M_TOK];
__device__ float g_bias2[H_DIM];
__device__ float g_h1[(size_t)M_TOK * H_DIM];
__device__ float g_h2[(size_t)M_TOK * H_DIM];
__device__ float g_h3[(size_t)M_TOK * Q_DIM];
// fp16-split weights, TRANSPOSED [n][k] layout (k contiguous)
__device__ __half g_W1h[H_DIM * C_DIM];
__device__ __half g_W1l[H_DIM * C_DIM];
__device__ __half g_W2h[H_DIM * H_DIM];
__device__ __half g_W2l[H_DIM * H_DIM];
__device__ __half g_W3h[Q_DIM * H_DIM];
__device__ __half g_W3l[Q_DIM * H_DIM];
__device__ int   g_fix_count;
__device__ int   g_fix_list[M_TOK];

// ----------------- helpers ------------------------------------------------
__device__ __forceinline__ float gelu_f(float v) {
    return 0.5f * v * (1.0f + erff(v * 0.70710678118654752440f));
}
__device__ __forceinline__ void h16split(float x, __half& h, __half& l) {
    h = __float2half_rn(x);
    l = __float2half_rn(x - __half2float(h));
}
__device__ __forceinline__ uint32_t pack2(__half a, __half b) {
    __half2 h2 = __halves2half2(a, b);
    return *reinterpret_cast<uint32_t*>(&h2);
}
#define CPA16(dst, src) \
    asm volatile("cp.async.cg.shared.global [%0], [%1], 16;" :: "r"(dst), "l"(src) : "memory")
#define CPA_COMMIT() asm volatile("cp.async.commit_group;" ::: "memory")
#define CPA_WAIT0()  asm volatile("cp.async.wait_group 0;" ::: "memory")
__device__ __forceinline__ uint32_t smem_u32(const void* p) {
    uint32_t a;
    asm("{ .reg .u64 t; cvta.to.shared.u64 t, %1; cvt.u32.u64 %0, t; }" : "=r"(a) : "l"(p));
    return a;
}
__device__ __forceinline__ void ldsm4(uint32_t* r, uint32_t addr) {
    asm volatile("ldmatrix.sync.aligned.m8n8.x4.shared.b16 {%0,%1,%2,%3}, [%4];"
                 : "=r"(r[0]), "=r"(r[1]), "=r"(r[2]), "=r"(r[3]) : "r"(addr));
}
__device__ __forceinline__ void mma16(float* d, const uint32_t* a, uint32_t b0, uint32_t b1) {
    asm volatile(
        "mma.sync.aligned.m16n8k16.row.col.f32.f16.f16.f32 "
        "{%0,%1,%2,%3}, {%4,%5,%6,%7}, {%8,%9}, {%0,%1,%2,%3};"
        : "+f"(d[0]), "+f"(d[1]), "+f"(d[2]), "+f"(d[3])
        : "r"(a[0]), "r"(a[1]), "r"(a[2]), "r"(a[3]), "r"(b0), "r"(b1));
}

// ----------------- LN stats ------------------------------------------------
__global__ __launch_bounds__(256)
void ln_stats_kernel(const float* __restrict__ x) {
    int row = (blockIdx.x * 256 + threadIdx.x) >> 5;
    int lane = threadIdx.x & 31;
    const float4* xr = (const float4*)(x + (size_t)row * C_DIM);
    float s = 0.f, ss = 0.f;
#pragma unroll
    for (int i = 0; i < C_DIM / 128; ++i) {
        float4 v = xr[lane + 32 * i];
        s  += v.x + v.y + v.z + v.w;
        ss += v.x * v.x + v.y * v.y + v.z * v.z + v.w * v.w;
    }
#pragma unroll
    for (int o = 16; o; o >>= 1) {
        s  += __shfl_xor_sync(0xffffffffu, s, o);
        ss += __shfl_xor_sync(0xffffffffu, ss, o);
    }
    if (lane == 0) {
        float mu = s * (1.0f / C_DIM);
        float var = ss * (1.0f / C_DIM) - mu * mu;
        g_mu[row] = mu;
        g_rstd[row] = rsqrtf(var + 1e-5f);
    }
}

// ----------------- weight prep: transpose + fp16 split ----------------------
__global__ void prep_w_kernel(const float* __restrict__ WL,
                              const float* __restrict__ Wl1,
                              const float* __restrict__ Wl2) {
    int i = blockIdx.x * blockDim.x + threadIdx.x;
    if (i == 0) g_fix_count = 0;
    const int S1 = H_DIM * C_DIM;
    const int S2 = S1 + H_DIM * H_DIM;
    const int S3 = S2 + Q_DIM * H_DIM;
    if (i < S1) {
        int n = i / C_DIM, k = i % C_DIM;
        h16split(WL[(size_t)k * H_DIM + n], g_W1h[i], g_W1l[i]);
    } else if (i < S2) {
        int j = i - S1;
        int n = j / H_DIM, k = j % H_DIM;          // Wl1 top half: rows 0..511
        h16split(Wl1[(size_t)k * H_DIM + n], g_W2h[j], g_W2l[j]);
    } else if (i < S3) {
        int j = i - S2;
        int n = j / H_DIM, k = j % H_DIM;
        h16split(Wl2[(size_t)k * Q_DIM + n], g_W3h[j], g_W3l[j]);
    }
}

// ----------------- bias2 = noise_feature @ W_l1[512:,:] (exact fp32) -------
__global__ void bias2_kernel(const float* __restrict__ nf,
                             const float* __restrict__ Wl1) {
    int j = blockIdx.x * blockDim.x + threadIdx.x;
    const float* wp = Wl1 + (size_t)H_DIM * H_DIM + j;
    float s = 0.f;
    for (int k = 0; k < H_DIM; ++k)
        s += nf[k] * wp[(size_t)k * H_DIM];
    g_bias2[j] = s;
}

// ----------------- split-fp16 mma.sync GEMM (ldmatrix fragments) -----------
// smem bytes: [0,1024): mu(128f)+rstd(128f)
//   A: base 1024, per buf 20480 (Ah 128 rows x 80B, Al same), 2 bufs
//   B: base 41984, per buf 20480 (Bh 128 rows x 80B, Bl same), 2 bufs
#define AB0 1024
#define BB0 41984
#define GEMM_SMEM 82944

template <int MODE>
__global__ __launch_bounds__(256, 2)
void gemm_mma(const float* __restrict__ Aext,
              const float* __restrict__ lns, const float* __restrict__ lnb) {
    constexpr int K  = (MODE == 0) ? C_DIM : H_DIM;
    constexpr int Nn = (MODE == 2) ? Q_DIM : H_DIM;
    constexpr int KB = K / 32;

    extern __shared__ char sm[];
    float* smf = (float*)sm;
    const uint32_t sb = smem_u32(sm);
    const int tid = threadIdx.x;
    const int wid = tid >> 5, lane = tid & 31;
    const int g = lane >> 2, tg = lane & 3;
    const int wm = wid & 3, wn = wid >> 2;
    const int m0 = blockIdx.y * 128, n0 = blockIdx.x * 128;

    const float* A    = (MODE == 0) ? Aext : (MODE == 1 ? g_h1 : g_h2);
    const __half* BhG = (MODE == 0) ? g_W1h : (MODE == 1 ? g_W2h : g_W3h);
    const __half* BlG = (MODE == 0) ? g_W1l : (MODE == 1 ? g_W2l : g_W3l);
    float* Cm         = (MODE == 0) ? g_h1 : (MODE == 1 ? g_h2 : g_h3);

    if (MODE == 0 && tid < 128) {
        smf[tid]       = g_mu[m0 + tid];
        smf[128 + tid] = g_rstd[m0 + tid];
    }

    // A staging: thread -> (row arow, 16-wide k half)
    const int arow = tid >> 1;
    const int ak   = (tid & 1) * 16;
    const float* aP = A + (size_t)(m0 + arow) * K + ak;
    // B staging: thread -> rows brow, brow+64; 16B chunk bq of 4
    const int brow = tid >> 2;
    const int bq   = tid & 3;
    const __half* bhP = BhG + (size_t)(n0 + brow) * K + bq * 8;
    const __half* blP = BlG + (size_t)(n0 + brow) * K + bq * 8;

    float4 aR[4];

    auto issueB = [&](int kb, int b) {
        uint32_t base = sb + BB0 + b * 20480 + brow * 80 + bq * 16;
        const __half* sh = bhP + kb * 32;
        const __half* sl = blP + kb * 32;
        CPA16(base,                 sh);
        CPA16(base + 64 * 80,       sh + (size_t)64 * K);
        CPA16(base + 10240,         sl);
        CPA16(base + 10240 + 64*80, sl + (size_t)64 * K);
    };
    auto loadA = [&](int kb) {
        const float* p = aP + kb * 32;
#pragma unroll
        for (int c = 0; c < 4; ++c) aR[c] = *(const float4*)(p + c * 4);
    };
    auto storeA = [&](int kb, int b) {
        char* dh = sm + AB0 + b * 20480 + arow * 80 + ak * 2;
        char* dl = dh + 10240;
        float mu = 0.f, rs = 0.f;
        if (MODE == 0) { mu = smf[arow]; rs = smf[128 + arow]; }
        uint32_t hw[8], lw[8];
#pragma unroll
        for (int c = 0; c < 4; ++c) {
            float4 v = aR[c];
            if (MODE == 0) {
                int k = kb * 32 + ak + c * 4;
                float4 s4 = *(const float4*)(lns + k);
                float4 b4 = *(const float4*)(lnb + k);
                v.x = (v.x - mu) * rs * s4.x + b4.x;
                v.y = (v.y - mu) * rs * s4.y + b4.y;
                v.z = (v.z - mu) * rs * s4.z + b4.z;
                v.w = (v.w - mu) * rs * s4.w + b4.w;
            }
            __half hx, lx, hy, ly, hz, lz, hwv, lwv;
            h16split(v.x, hx, lx); h16split(v.y, hy, ly);
            h16split(v.z, hz, lz); h16split(v.w, hwv, lwv);
            hw[c * 2]     = pack2(hx, hy);
            hw[c * 2 + 1] = pack2(hz, hwv);
            lw[c * 2]     = pack2(lx, ly);
            lw[c * 2 + 1] = pack2(lz, lwv);
        }
        *(uint4*)(dh)      = make_uint4(hw[0], hw[1], hw[2], hw[3]);
        *(uint4*)(dh + 16) = make_uint4(hw[4], hw[5], hw[6], hw[7]);
        *(uint4*)(dl)      = make_uint4(lw[0], lw[1], lw[2], lw[3]);
        *(uint4*)(dl + 16) = make_uint4(lw[4], lw[5], lw[6], lw[7]);
    };

    float acc[2][8][4];
#pragma unroll
    for (int mt = 0; mt < 2; ++mt)
#pragma unroll
        for (int nt = 0; nt < 8; ++nt)
#pragma unroll
            for (int j = 0; j < 4; ++j) acc[mt][nt][j] = 0.f;

    // ldmatrix lane-address components
    const int aRowL = lane & 15;            // A: fragment row within m16
    const int aKhL  = lane >> 4;            // A: k-half (0/1)
    const int bRowL = (lane & 7) + ((lane >> 4) << 3);  // B: n row within n16
    const int bKbL  = (lane >> 3) & 1;      // B: k block (0/1)

    auto compute = [&](int b) {
        const uint32_t baseAh = sb + AB0 + b * 20480;
        const uint32_t baseAl = baseAh + 10240;
        const uint32_t baseBh = sb + BB0 + b * 20480;
        const uint32_t baseBl = baseBh + 10240;
#pragma unroll
        for (int ck = 0; ck < 2; ++ck) {
            const int k0 = ck * 16;
            const uint32_t aoff = (uint32_t)(aRowL * 80 + (k0 + aKhL * 8) * 2);
            const uint32_t boff = (uint32_t)(bRowL * 80 + (k0 + bKbL * 8) * 2);
            uint32_t ah[2][4], al[2][4];
#pragma unroll
            for (int mt = 0; mt < 2; ++mt) {
                uint32_t ro = (uint32_t)((wm * 32 + mt * 16) * 80);
                ldsm4(ah[mt], baseAh + ro + aoff);
                ldsm4(al[mt], baseAl + ro + aoff);
            }
#pragma unroll
            for (int p = 0; p < 4; ++p) {   // n16 groups -> nt pairs (2p, 2p+1)
                uint32_t co = (uint32_t)((wn * 64 + p * 16) * 80);
                uint32_t bh4[4], bl4[4];
                ldsm4(bh4, baseBh + co + boff);
                ldsm4(bl4, baseBl + co + boff);
#pragma unroll
                for (int q = 0; q < 2; ++q) {
                    const int nt = p * 2 + q;
                    const uint32_t b0h = bh4[q * 2], b1h = bh4[q * 2 + 1];
                    const uint32_t b0l = bl4[q * 2], b1l = bl4[q * 2 + 1];
#pragma unroll
                    for (int mt = 0; mt < 2; ++mt) {
                        mma16(acc[mt][nt], ah[mt], b0h, b1h);
                        mma16(acc[mt][nt], ah[mt], b0l, b1l);
                        mma16(acc[mt][nt], al[mt], b0h, b1h);
                    }
                }
            }
        }
    };

    // ---- pipeline ----
    issueB(0, 0);
    CPA_COMMIT();
    loadA(0);
    __syncthreads();          // mu/rstd visible
    storeA(0, 0);
    CPA_WAIT0();
    __syncthreads();

    int buf = 0;
    for (int kt = 0; kt < KB; ++kt) {
        if (kt + 1 < KB) {
            issueB(kt + 1, buf ^ 1);
            CPA_COMMIT();
            loadA(kt + 1);
        }
        compute(buf);
        if (kt + 1 < KB) storeA(kt + 1, buf ^ 1);
        CPA_WAIT0();
        __syncthreads();
        buf ^= 1;
    }

    // ---- epilogue ----
#pragma unroll
    for (int mt = 0; mt < 2; ++mt) {
        int r = m0 + wm * 32 + mt * 16 + g;
#pragma unroll
        for (int nt = 0; nt < 8; ++nt) {
            int c = n0 + wn * 64 + nt * 8 + tg * 2;
            float* a4 = acc[mt][nt];
            float b0 = 0.f, b1 = 0.f;
            if (MODE == 1) { b0 = g_bias2[c]; b1 = g_bias2[c + 1]; }
            float2 v0 = make_float2(gelu_f(a4[0] + b0), gelu_f(a4[1] + b1));
            float2 v1 = make_float2(gelu_f(a4[2] + b0), gelu_f(a4[3] + b1));
            *(float2*)(Cm + (size_t)r * Nn + c)       = v0;
            *(float2*)(Cm + (size_t)(r + 8) * Nn + c) = v1;
        }
    }
}

// ----------------- final: logit, flag-or-write -----------------------------
__global__ __launch_bounds__(256)
void final_kernel(const float* __restrict__ x, const float* __restrict__ prevm,
                  const float* __restrict__ w3, float* __restrict__ out,
                  int write_extra) {
    int row = (blockIdx.x * 256 + threadIdx.x) >> 5;
    int lane = threadIdx.x & 31;
    const float* h3 = g_h3 + (size_t)row * Q_DIM;
    float s = 0.f;
#pragma unroll
    for (int i = 0; i < 8; ++i) s += h3[lane + 32 * i] * w3[lane + 32 * i];
#pragma unroll
    for (int o = 16; o; o >>= 1) s += __shfl_xor_sync(0xffffffffu, s, o);

    float prob = 1.0f / (1.0f + expf(-s));
    float xm = prob * prevm[row];

    if (fabsf(xm - 0.5f) < 2e-4f) {
        if (lane == 0) {
            int idx = atomicAdd(&g_fix_count, 1);
            if (idx < M_TOK) g_fix_list[idx] = row;
        }
        return;
    }
    float m = (xm > 0.5f) ? 1.0f : 0.0f;
    if (lane == 0 && write_extra) {
        out[(size_t)M_TOK * C_DIM + row] = m;
        out[(size_t)M_TOK * C_DIM + M_TOK + row] = (m > 0.f) ? 1.0f : 1e-10f;
    }
    const float4* xr = (const float4*)(x + (size_t)row * C_DIM);
    float4* orow = (float4*)(out + (size_t)row * C_DIM);
#pragma unroll
    for (int i = 0; i < 8; ++i) {
        float4 v = xr[lane + 32 * i];
        v.x *= m; v.y *= m; v.z *= m; v.w *= m;
        orow[lane + 32 * i] = v;
    }
}

// ----------------- fixup: exact fp32 recompute for flagged rows ------------
__global__ __launch_bounds__(256)
void fixup_kernel(const float* __restrict__ x, const float* __restrict__ prevm,
                  const float* __restrict__ WL, const float* __restrict__ Wl1,
                  const float* __restrict__ Wl2, const float* __restrict__ w3,
                  const float* __restrict__ lns, const float* __restrict__ lnb,
                  float* __restrict__ out, int write_extra) {
    __shared__ float a[C_DIM];
    __shared__ float h1s[H_DIM];
    __shared__ float h2s[H_DIM];
    __shared__ float h3s[Q_DIM];
    __shared__ float red[256];
    int cnt = g_fix_count;
    if (cnt > M_TOK) cnt = M_TOK;
    int t = threadIdx.x;

    for (int i = blockIdx.x; i < cnt; i += gridDim.x) {
        int row = g_fix_list[i];
        float mu = g_mu[row], rs = g_rstd[row];
        for (int j = t; j < C_DIM; j += 256)
            a[j] = (x[(size_t)row * C_DIM + j] - mu) * rs * lns[j] + lnb[j];
        __syncthreads();
        for (int j = t; j < H_DIM; j += 256) {
            float acc = 0.f;
            for (int k = 0; k < C_DIM; ++k)
                acc = fmaf(a[k], WL[(size_t)k * H_DIM + j], acc);
            h1s[j] = gelu_f(acc);
        }
        __syncthreads();
        for (int j = t; j < H_DIM; j += 256) {
            float acc = g_bias2[j];
            for (int k = 0; k < H_DIM; ++k)
                acc = fmaf(h1s[k], Wl1[(size_t)k * H_DIM + j], acc);
            h2s[j] = gelu_f(acc);
        }
        __syncthreads();
        for (int j = t; j < Q_DIM; j += 256) {
            float acc = 0.f;
            for (int k = 0; k < H_DIM; ++k)
                acc = fmaf(h2s[k], Wl2[(size_t)k * Q_DIM + j], acc);
            h3s[j] = gelu_f(acc);
        }
        __syncthreads();
        red[t] = (t < Q_DIM) ? h3s[t] * w3[t] : 0.f;
        __syncthreads();
        for (int o = 128; o; o >>= 1) {
            if (t < o) red[t] += red[t + o];
            __syncthreads();
        }
        float s = red[0];
        float prob = 1.0f / (1.0f + expf(-s));
        float m = (prob * prevm[row] > 0.5f) ? 1.0f : 0.0f;
        if (t == 0 && write_extra) {
            out[(size_t)M_TOK * C_DIM + row] = m;
            out[(size_t)M_TOK * C_DIM + M_TOK + row] = (m > 0.f) ? 1.0f : 1e-10f;
        }
        for (int j = t; j < C_DIM; j += 256)
            out[(size_t)row * C_DIM + j] = x[(size_t)row * C_DIM + j] * m;
        __syncthreads();
    }
}

// ----------------- launch ---------------------------------------------------
extern "C" void kernel_launch(void* const* d_in, const int* in_sizes, int n_in,
                              void* d_out, int out_size) {
    const float* x   = (const float*)d_in[0];
    const float* nf  = (const float*)d_in[1];
    const float* pm  = (const float*)d_in[2];
    const float* lns = (const float*)d_in[3];
    const float* lnb = (const float*)d_in[4];
    const float* WL  = (const float*)d_in[5];
    const float* Wl1 = (const float*)d_in[6];
    const float* Wl2 = (const float*)d_in[7];
    const float* W3  = (const float*)d_in[8];
    float* out = (float*)d_out;

    cudaFuncSetAttribute(gemm_mma<0>, cudaFuncAttributeMaxDynamicSharedMemorySize, GEMM_SMEM);
    cudaFuncSetAttribute(gemm_mma<1>, cudaFuncAttributeMaxDynamicSharedMemorySize, GEMM_SMEM);
    cudaFuncSetAttribute(gemm_mma<2>, cudaFuncAttributeMaxDynamicSharedMemorySize, GEMM_SMEM);

    ln_stats_kernel<<<M_TOK / 8, 256>>>(x);
    prep_w_kernel<<<(H_DIM * C_DIM + H_DIM * H_DIM + Q_DIM * H_DIM + 255) / 256, 256>>>(WL, Wl1, Wl2);
    bias2_kernel<<<2, 256>>>(nf, Wl1);

    gemm_mma<0><<<dim3(H_DIM / 128, M_TOK / 128), 256, GEMM_SMEM>>>(x, lns, lnb);
    gemm_mma<1><<<dim3(H_DIM / 128, M_TOK / 128), 256, GEMM_SMEM>>>(nullptr, nullptr, nullptr);
    gemm_mma<2><<<dim3(Q_DIM / 128, M_TOK / 128), 256, GEMM_SMEM>>>(nullptr, nullptr, nullptr);

    int extra = (out_size >= M_TOK * C_DIM + 2 * M_TOK) ? 1 : 0;
    final_kernel<<<M_TOK / 8, 256>>>(x, pm, W3, out, extra);
    fixup_kernel<<<512, 256>>>(x, pm, WL, Wl1, Wl2, W3, lns, lnb, out, extra);
}